// round 8
// baseline (speedup 1.0000x reference)
#include <cuda_runtime.h>

// ===================== Problem constants =====================
// M=3, N=8, G=8, K=3
// x: (32, 3, 224, 224) f32   w: (24, 1, 3, 3) f32
// out: (32, 192, 222, 222) f32, grouped conv: out channel o uses in channel o/64

#define IMG 224
#define OUT 222
#define NCH 192
#define PLANE_OUT (OUT*OUT)        // 49284 elems; x4B = 197136 B ≡ 0 mod 16

typedef unsigned long long u64;

// duplicated rotated weights (w,w) as u64, padded layout [192][10]:
// g_rotw2[o*10 + j], j<9 real (dy*3+dx), j==9 zero pad -> 80B stride, 16B aligned
__device__ u64 g_rotw2[192 * 10];

__device__ __forceinline__ u64 ffma2(u64 a, u64 b, u64 c) {
    u64 d;
    asm("fma.rn.f32x2 %0, %1, %2, %3;" : "=l"(d) : "l"(a), "l"(b), "l"(c));
    return d;
}
__device__ __forceinline__ u64 pack2(float lo, float hi) {
    u64 d;
    asm("mov.b64 %0, {%1, %2};" : "=l"(d) : "f"(lo), "f"(hi));
    return d;
}

// ===================== Kernel 1: rotate weights =====================
__global__ void rotw_kernel(const float* __restrict__ w) {
    int t = blockIdx.x * blockDim.x + threadIdx.x;
    if (t >= 192 * 10) return;
    int o = t / 10, j = t % 10;
    if (j == 9) { g_rotw2[t] = 0ull; return; }   // pad slot
    int mn = o >> 3, g = o & 7;
    int hh = j / 3, ww = j % 3;

    // angle: linspace(-90, 90, 8)[g] degrees -> radians (double, like numpy)
    double ang = (-90.0 + (180.0 / 7.0) * (double)g) * 0.017453292519943295;
    float c = (float)cos(ang);
    float s = (float)sin(ang);

    float cx = (2.0f * ww + 1.0f) / 3.0f - 1.0f;
    float cy = (2.0f * hh + 1.0f) / 3.0f - 1.0f;
    float gx = c * cx - s * cy;
    float gy = s * cx + c * cy;

    float ix = ((gx + 1.0f) * 3.0f - 1.0f) * 0.5f;
    float iy = ((gy + 1.0f) * 3.0f - 1.0f) * 0.5f;
    float x0f = floorf(ix), y0f = floorf(iy);
    int   x0  = (int)x0f,   y0  = (int)y0f;
    float wx1 = ix - x0f, wy1 = iy - y0f;
    float wx0 = 1.0f - wx1, wy0 = 1.0f - wy1;

    const float* wp = w + mn * 9;
    float v00 = 0.f, v10 = 0.f, v01 = 0.f, v11 = 0.f;
    int x1 = x0 + 1, y1 = y0 + 1;
    bool bx0 = (x0 >= 0 && x0 < 3), bx1 = (x1 >= 0 && x1 < 3);
    bool by0 = (y0 >= 0 && y0 < 3), by1 = (y1 >= 0 && y1 < 3);
    if (bx0 && by0) v00 = wp[y0 * 3 + x0];
    if (bx1 && by0) v10 = wp[y0 * 3 + x1];
    if (bx0 && by1) v01 = wp[y1 * 3 + x0];
    if (bx1 && by1) v11 = wp[y1 * 3 + x1];

    float v = v00 * (wx0 * wy0) + v10 * (wx1 * wy0)
            + v01 * (wx0 * wy1) + v11 * (wx1 * wy1);

    g_rotw2[t] = pack2(v, v);
}

// ===================== Kernel 2: grouped conv, FULL-WIDTH tiles =====================
// CTA: 224 threads = 56 x-threads x 4 y-threads. Tile = full 222-wide x 8 rows,
// all 64 channels of group m.
// Thread: 4 cols x 2 consecutive rows. Even row (16B-aligned) -> STG.128,
// odd row -> 2x STG.64. Weights: 5 vector LDS per channel (4x .128 + 1x .64).
#define TH 8
#define IN_H 10    // 8 + 2 halo rows

__global__ void __launch_bounds__(224)
conv_kernel(const float* __restrict__ x, float* __restrict__ out) {
    __shared__ __align__(16) float s_in[IN_H * IMG + 2];  // +2 pad for edge-lane reads
    __shared__ __align__(16) u64   s_w[64 * 10];          // 5120 B

    int nm  = blockIdx.z;          // n*3 + m
    int m   = nm % 3;
    int ty0 = blockIdx.y * TH;     // first output row of tile (multiple of 8)
    int tid = threadIdx.x;

    const float* xp = x + (size_t)nm * (IMG * IMG);

    // cooperative input load: full 224-wide rows, perfectly coalesced.
    for (int i = tid; i < IN_H * IMG; i += 224) {
        int r  = i / IMG, cc = i % IMG;
        int gr = ty0 + r;  if (gr > IMG - 1) gr = IMG - 1;   // row clamp (last tile only)
        s_in[i] = xp[gr * IMG + cc];
    }
    // weights for this group (padded duplicated-pair layout)
    {
        const u64* gw = g_rotw2 + (size_t)m * 64 * 10;
        for (int i = tid; i < 64 * 10; i += 224) s_w[i] = gw[i];
    }
    __syncthreads();

    int xi = tid % 56;             // 0..55
    int yi = tid / 56;             // 0..3
    int lx = 4 * xi;               // 0,4,...,220
    int ly = 2 * yi;               // 0,2,4,6
    int oy = ty0 + ly;             // even
    if (oy >= OUT) return;         // rows 222/223 in last tile; no syncs follow
    // oy valid => oy <= 220 => oy+1 <= 221 valid: no row predicates needed.
    bool full = (xi < 55);         // xi==55: cols 220-221 pair only

    // input pairs: 4 rows (ly..ly+3), 5 overlapping pairs per row.
    // p[r][k] = (f_k, f_{k+1}) where f_j = s_in[(ly+r)*224 + lx + j]
    u64 p[4][5];
#pragma unroll
    for (int r = 0; r < 4; r++) {
        const float* rowp = &s_in[(ly + r) * IMG + lx];   // 16B aligned
        float4 q = *(const float4*)rowp;
        float f4 = rowp[4], f5 = rowp[5];                 // edge lane: pad-safe
        p[r][0] = pack2(q.x, q.y);
        p[r][1] = pack2(q.y, q.z);
        p[r][2] = pack2(q.z, q.w);
        p[r][3] = pack2(q.w, f4);
        p[r][4] = pack2(f4, f5);
    }

    int n = nm / 3;
    float* outp = out + (size_t)(n * NCH + m * 64) * PLANE_OUT
                      + (size_t)oy * OUT + lx;

    for (int c = 0; c < 64; c++) {
        const u64* wc = &s_w[c * 10];                     // 80B stride, 16B aligned
        ulonglong2 wA = *(const ulonglong2*)(wc + 0);     // w0 w1
        ulonglong2 wB = *(const ulonglong2*)(wc + 2);     // w2 w3
        ulonglong2 wC = *(const ulonglong2*)(wc + 4);     // w4 w5
        ulonglong2 wD = *(const ulonglong2*)(wc + 6);     // w6 w7
        u64 wv[9] = { wA.x, wA.y, wB.x, wB.y, wC.x, wC.y, wD.x, wD.y, wc[8] };

        u64 a00 = 0, a01 = 0, a10 = 0, a11 = 0;
#pragma unroll
        for (int dy = 0; dy < 3; dy++) {
#pragma unroll
            for (int dx = 0; dx < 3; dx++) {
                u64 wt = wv[dy * 3 + dx];
                a00 = ffma2(p[dy][dx],         wt, a00);  // row0, cols lx..lx+1
                a01 = ffma2(p[dy][dx + 2],     wt, a01);  // row0, cols lx+2..lx+3
                a10 = ffma2(p[dy + 1][dx],     wt, a10);  // row1, cols lx..lx+1
                a11 = ffma2(p[dy + 1][dx + 2], wt, a11);  // row1, cols lx+2..lx+3
            }
        }

        if (full) {
            *(ulonglong2*)(outp) = make_ulonglong2(a00, a01);  // even row: STG.128
            *(u64*)(outp + OUT)     = a10;                     // odd row: 2x STG.64
            *(u64*)(outp + OUT + 2) = a11;
        } else {
            *(u64*)(outp)       = a00;                         // cols 220-221
            *(u64*)(outp + OUT) = a10;
        }
        outp += PLANE_OUT;
    }
}

// ===================== launch =====================
extern "C" void kernel_launch(void* const* d_in, const int* in_sizes, int n_in,
                              void* d_out, int out_size) {
    const float* x = (const float*)d_in[0];
    const float* w = (const float*)d_in[1];
    float* out = (float*)d_out;

    rotw_kernel<<<8, 256>>>(w);    // 192*10 = 1920 slots

    dim3 grid(1,
              (OUT + TH - 1) / TH,   // 28 full-width row tiles
              32 * 3);               // 96 (n,m) planes
    conv_kernel<<<grid, 224>>>(x, out);
}

// round 9
// speedup vs baseline: 1.2925x; 1.2925x over previous
#include <cuda_runtime.h>

// ===================== Problem constants =====================
// M=3, N=8, G=8, K=3
// x: (32, 3, 224, 224) f32   w: (24, 1, 3, 3) f32
// out: (32, 192, 222, 222) f32, grouped conv: out channel o uses in channel o/64

#define IMG 224
#define OUT 222
#define NCH 192
#define PLANE_OUT (OUT*OUT)        // 49284

typedef unsigned long long u64;

// duplicated rotated weights (w,w) as u64, padded layout [192][10]:
// g_rotw2[o*10 + j], j<9 real (dy*3+dx), j==9 zero pad -> 80B stride, 16B aligned
__device__ u64 g_rotw2[192 * 10];

__device__ __forceinline__ u64 ffma2(u64 a, u64 b, u64 c) {
    u64 d;
    asm("fma.rn.f32x2 %0, %1, %2, %3;" : "=l"(d) : "l"(a), "l"(b), "l"(c));
    return d;
}
__device__ __forceinline__ u64 pack2(float lo, float hi) {
    u64 d;
    asm("mov.b64 %0, {%1, %2};" : "=l"(d) : "f"(lo), "f"(hi));
    return d;
}
__device__ __forceinline__ void unpack2(u64 v, float& lo, float& hi) {
    asm("mov.b64 {%0, %1}, %2;" : "=f"(lo), "=f"(hi) : "l"(v));
}

// ===================== Kernel 1: rotate weights =====================
__global__ void rotw_kernel(const float* __restrict__ w) {
    int t = blockIdx.x * blockDim.x + threadIdx.x;
    if (t >= 192 * 10) return;
    int o = t / 10, j = t % 10;
    if (j == 9) { g_rotw2[t] = 0ull; return; }   // pad slot
    int mn = o >> 3, g = o & 7;
    int hh = j / 3, ww = j % 3;

    // angle: linspace(-90, 90, 8)[g] degrees -> radians (double, like numpy)
    double ang = (-90.0 + (180.0 / 7.0) * (double)g) * 0.017453292519943295;
    float c = (float)cos(ang);
    float s = (float)sin(ang);

    float cx = (2.0f * ww + 1.0f) / 3.0f - 1.0f;
    float cy = (2.0f * hh + 1.0f) / 3.0f - 1.0f;
    float gx = c * cx - s * cy;
    float gy = s * cx + c * cy;

    float ix = ((gx + 1.0f) * 3.0f - 1.0f) * 0.5f;
    float iy = ((gy + 1.0f) * 3.0f - 1.0f) * 0.5f;
    float x0f = floorf(ix), y0f = floorf(iy);
    int   x0  = (int)x0f,   y0  = (int)y0f;
    float wx1 = ix - x0f, wy1 = iy - y0f;
    float wx0 = 1.0f - wx1, wy0 = 1.0f - wy1;

    const float* wp = w + mn * 9;
    float v00 = 0.f, v10 = 0.f, v01 = 0.f, v11 = 0.f;
    int x1 = x0 + 1, y1 = y0 + 1;
    bool bx0 = (x0 >= 0 && x0 < 3), bx1 = (x1 >= 0 && x1 < 3);
    bool by0 = (y0 >= 0 && y0 < 3), by1 = (y1 >= 0 && y1 < 3);
    if (bx0 && by0) v00 = wp[y0 * 3 + x0];
    if (bx1 && by0) v10 = wp[y0 * 3 + x1];
    if (bx0 && by1) v01 = wp[y1 * 3 + x0];
    if (bx1 && by1) v11 = wp[y1 * 3 + x1];

    float v = v00 * (wx0 * wy0) + v10 * (wx1 * wy0)
            + v01 * (wx0 * wy1) + v11 * (wx1 * wy1);

    g_rotw2[t] = pack2(v, v);
}

// ===================== Kernel 2: grouped conv, FULL-WIDTH tiles =====================
// R7 geometry (proven): CTA 224 threads = 112 x-threads x 2 y-threads.
// Tile = full 222-wide x 8 rows, all 64 channels of group m.
// Thread: 1 col-pair x 4 rows, STG.64 stores (warp = 32 consecutive pairs =
// one contiguous 256B segment per store).
// ONLY change vs R7: weights fetched as 4x LDS.128 + 1x LDS.64 (padded stride).
#define TH 8
#define IN_H 10    // 8 + 2 halo rows

__global__ void __launch_bounds__(224)
conv_kernel(const float* __restrict__ x, float* __restrict__ out) {
    __shared__ __align__(16) float s_in[IN_H * IMG];   // 8960 B
    __shared__ __align__(16) u64   s_w[64 * 10];       // 5120 B

    int nm  = blockIdx.z;          // n*3 + m
    int m   = nm % 3;
    int ty0 = blockIdx.y * TH;     // first output row of tile
    int tid = threadIdx.x;

    const float* xp = x + (size_t)nm * (IMG * IMG);

    // cooperative input load: 224 threads = exactly one full 896B row per pass.
    for (int i = tid; i < IN_H * IMG; i += 224) {
        int r  = i / IMG, cc = i % IMG;
        int gr = ty0 + r;  if (gr > IMG - 1) gr = IMG - 1;   // row clamp (last tile only)
        s_in[i] = xp[gr * IMG + cc];
    }
    // weights for this group (padded duplicated-pair layout, 80B/channel)
    {
        const u64* gw = g_rotw2 + (size_t)m * 64 * 10;
        for (int i = tid; i < 64 * 10; i += 224) s_w[i] = gw[i];
    }
    __syncthreads();

    int xi = tid % 112;            // col-pair index
    int yi = tid / 112;            // 0..1
    if (xi >= 111) return;         // pair 111 = cols 222-223 (invalid); no syncs follow
    int ox = 2 * xi;
    int ly = 4 * yi;               // 0 or 4
    int oy = ty0 + ly;             // rows oy, oy+1 always valid (oy <= 220)
    bool rv2 = (oy + 2) < OUT;     // false only in last y-tile
    bool rv3 = (oy + 3) < OUT;

    // register-resident input pairs: rows ly..ly+5, 3 overlapping pairs each
    u64 ip[6][3];
#pragma unroll
    for (int r = 0; r < 6; r++) {
        const u64* p = (const u64*)&s_in[(ly + r) * IMG + ox];   // 8B aligned
        u64 a = p[0], b = p[1];
        float a0, a1, a2, a3;
        unpack2(a, a0, a1);
        unpack2(b, a2, a3);
        ip[r][0] = a;
        ip[r][1] = pack2(a1, a2);
        ip[r][2] = b;
    }

    int n = nm / 3;
    float* outp = out + (size_t)(n * NCH + m * 64) * PLANE_OUT
                      + (size_t)oy * OUT + ox;

    for (int c = 0; c < 64; c++) {
        // 5 vector LDS instead of 9 scalar: 80B stride keeps rows 16B aligned
        const u64* wc = &s_w[c * 10];
        ulonglong2 wA = *(const ulonglong2*)(wc + 0);   // w0 w1
        ulonglong2 wB = *(const ulonglong2*)(wc + 2);   // w2 w3
        ulonglong2 wC = *(const ulonglong2*)(wc + 4);   // w4 w5
        ulonglong2 wD = *(const ulonglong2*)(wc + 6);   // w6 w7
        u64 w8 = wc[8];
        u64 wv[9] = { wA.x, wA.y, wB.x, wB.y, wC.x, wC.y, wD.x, wD.y, w8 };

        u64 acc0 = 0, acc1 = 0, acc2 = 0, acc3 = 0;
#pragma unroll
        for (int dy = 0; dy < 3; dy++) {
#pragma unroll
            for (int dx = 0; dx < 3; dx++) {
                u64 wt = wv[dy * 3 + dx];
                acc0 = ffma2(ip[0 + dy][dx], wt, acc0);
                acc1 = ffma2(ip[1 + dy][dx], wt, acc1);
                acc2 = ffma2(ip[2 + dy][dx], wt, acc2);
                acc3 = ffma2(ip[3 + dy][dx], wt, acc3);
            }
        }
        *(u64*)(outp)                    = acc0;
        *(u64*)(outp + OUT)              = acc1;
        if (rv2) *(u64*)(outp + 2 * OUT) = acc2;
        if (rv3) *(u64*)(outp + 3 * OUT) = acc3;
        outp += PLANE_OUT;
    }
}

// ===================== launch =====================
extern "C" void kernel_launch(void* const* d_in, const int* in_sizes, int n_in,
                              void* d_out, int out_size) {
    const float* x = (const float*)d_in[0];
    const float* w = (const float*)d_in[1];
    float* out = (float*)d_out;

    rotw_kernel<<<8, 256>>>(w);    // 192*10 = 1920 slots

    dim3 grid(1,
              (OUT + TH - 1) / TH,   // 28 full-width row tiles
              32 * 3);               // 96 (n,m) planes
    conv_kernel<<<grid, 224>>>(x, out);
}

// round 10
// speedup vs baseline: 1.3324x; 1.0309x over previous
#include <cuda_runtime.h>

// ===================== Problem constants =====================
// M=3, N=8, G=8, K=3
// x: (32, 3, 224, 224) f32   w: (24, 1, 3, 3) f32
// out: (32, 192, 222, 222) f32, grouped conv: out channel o uses in channel o/64

#define IMG 224
#define OUT 222
#define NCH 192
#define PLANE_OUT (OUT*OUT)        // 49284

typedef unsigned long long u64;

// duplicated rotated weights (w,w) as u64, padded layout [192][10]:
// g_rotw2[o*10 + j], j<9 real (dy*3+dx), j==9 zero pad -> 80B stride, 16B aligned
__device__ u64 g_rotw2[192 * 10];

__device__ __forceinline__ u64 ffma2(u64 a, u64 b, u64 c) {
    u64 d;
    asm("fma.rn.f32x2 %0, %1, %2, %3;" : "=l"(d) : "l"(a), "l"(b), "l"(c));
    return d;
}
__device__ __forceinline__ u64 pack2(float lo, float hi) {
    u64 d;
    asm("mov.b64 %0, {%1, %2};" : "=l"(d) : "f"(lo), "f"(hi));
    return d;
}
__device__ __forceinline__ void unpack2(u64 v, float& lo, float& hi) {
    asm("mov.b64 {%0, %1}, %2;" : "=f"(lo), "=f"(hi) : "l"(v));
}
// streaming store: output is write-once, never re-read -> evict-first in L2
__device__ __forceinline__ void st_cs64(float* p, u64 v) {
    asm volatile("st.global.cs.b64 [%0], %1;" :: "l"(p), "l"(v) : "memory");
}

// ===================== Kernel 1: rotate weights =====================
__global__ void rotw_kernel(const float* __restrict__ w) {
    int t = blockIdx.x * blockDim.x + threadIdx.x;
    if (t >= 192 * 10) return;
    int o = t / 10, j = t % 10;
    if (j == 9) { g_rotw2[t] = 0ull; return; }   // pad slot
    int mn = o >> 3, g = o & 7;
    int hh = j / 3, ww = j % 3;

    // angle: linspace(-90, 90, 8)[g] degrees -> radians (double, like numpy)
    double ang = (-90.0 + (180.0 / 7.0) * (double)g) * 0.017453292519943295;
    float c = (float)cos(ang);
    float s = (float)sin(ang);

    float cx = (2.0f * ww + 1.0f) / 3.0f - 1.0f;
    float cy = (2.0f * hh + 1.0f) / 3.0f - 1.0f;
    float gx = c * cx - s * cy;
    float gy = s * cx + c * cy;

    float ix = ((gx + 1.0f) * 3.0f - 1.0f) * 0.5f;
    float iy = ((gy + 1.0f) * 3.0f - 1.0f) * 0.5f;
    float x0f = floorf(ix), y0f = floorf(iy);
    int   x0  = (int)x0f,   y0  = (int)y0f;
    float wx1 = ix - x0f, wy1 = iy - y0f;
    float wx0 = 1.0f - wx1, wy0 = 1.0f - wy1;

    const float* wp = w + mn * 9;
    float v00 = 0.f, v10 = 0.f, v01 = 0.f, v11 = 0.f;
    int x1 = x0 + 1, y1 = y0 + 1;
    bool bx0 = (x0 >= 0 && x0 < 3), bx1 = (x1 >= 0 && x1 < 3);
    bool by0 = (y0 >= 0 && y0 < 3), by1 = (y1 >= 0 && y1 < 3);
    if (bx0 && by0) v00 = wp[y0 * 3 + x0];
    if (bx1 && by0) v10 = wp[y0 * 3 + x1];
    if (bx0 && by1) v01 = wp[y1 * 3 + x0];
    if (bx1 && by1) v11 = wp[y1 * 3 + x1];

    float v = v00 * (wx0 * wy0) + v10 * (wx1 * wy0)
            + v01 * (wx0 * wy1) + v11 * (wx1 * wy1);

    g_rotw2[t] = pack2(v, v);
}

// ===================== Kernel 2: grouped conv, FULL-WIDTH tiles =====================
// R9 geometry (proven 250us): CTA 224 threads = 112 x-threads x 2 y-threads.
// Tile = full 222-wide x 8 rows, all 64 channels of group m.
// Thread: 1 col-pair x 4 rows, STG.64 stores (warp = 32 consecutive pairs =
// one contiguous 256B segment per store). Weights: 4x LDS.128 + 1x LDS.64.
// ONLY change vs R9: stores use st.global.cs (streaming / evict-first).
#define TH 8
#define IN_H 10    // 8 + 2 halo rows

__global__ void __launch_bounds__(224)
conv_kernel(const float* __restrict__ x, float* __restrict__ out) {
    __shared__ __align__(16) float s_in[IN_H * IMG];   // 8960 B
    __shared__ __align__(16) u64   s_w[64 * 10];       // 5120 B

    int nm  = blockIdx.z;          // n*3 + m
    int m   = nm % 3;
    int ty0 = blockIdx.y * TH;     // first output row of tile
    int tid = threadIdx.x;

    const float* xp = x + (size_t)nm * (IMG * IMG);

    // cooperative input load: 224 threads = exactly one full 896B row per pass.
    for (int i = tid; i < IN_H * IMG; i += 224) {
        int r  = i / IMG, cc = i % IMG;
        int gr = ty0 + r;  if (gr > IMG - 1) gr = IMG - 1;   // row clamp (last tile only)
        s_in[i] = xp[gr * IMG + cc];
    }
    // weights for this group (padded duplicated-pair layout, 80B/channel)
    {
        const u64* gw = g_rotw2 + (size_t)m * 64 * 10;
        for (int i = tid; i < 64 * 10; i += 224) s_w[i] = gw[i];
    }
    __syncthreads();

    int xi = tid % 112;            // col-pair index
    int yi = tid / 112;            // 0..1
    if (xi >= 111) return;         // pair 111 = cols 222-223 (invalid); no syncs follow
    int ox = 2 * xi;
    int ly = 4 * yi;               // 0 or 4
    int oy = ty0 + ly;             // rows oy, oy+1 always valid (oy <= 220)
    bool rv2 = (oy + 2) < OUT;     // false only in last y-tile
    bool rv3 = (oy + 3) < OUT;

    // register-resident input pairs: rows ly..ly+5, 3 overlapping pairs each
    u64 ip[6][3];
#pragma unroll
    for (int r = 0; r < 6; r++) {
        const u64* p = (const u64*)&s_in[(ly + r) * IMG + ox];   // 8B aligned
        u64 a = p[0], b = p[1];
        float a0, a1, a2, a3;
        unpack2(a, a0, a1);
        unpack2(b, a2, a3);
        ip[r][0] = a;
        ip[r][1] = pack2(a1, a2);
        ip[r][2] = b;
    }

    int n = nm / 3;
    float* outp = out + (size_t)(n * NCH + m * 64) * PLANE_OUT
                      + (size_t)oy * OUT + ox;

    for (int c = 0; c < 64; c++) {
        // 5 vector LDS: 80B stride keeps rows 16B aligned
        const u64* wc = &s_w[c * 10];
        ulonglong2 wA = *(const ulonglong2*)(wc + 0);   // w0 w1
        ulonglong2 wB = *(const ulonglong2*)(wc + 2);   // w2 w3
        ulonglong2 wC = *(const ulonglong2*)(wc + 4);   // w4 w5
        ulonglong2 wD = *(const ulonglong2*)(wc + 6);   // w6 w7
        u64 w8 = wc[8];
        u64 wv[9] = { wA.x, wA.y, wB.x, wB.y, wC.x, wC.y, wD.x, wD.y, w8 };

        u64 acc0 = 0, acc1 = 0, acc2 = 0, acc3 = 0;
#pragma unroll
        for (int dy = 0; dy < 3; dy++) {
#pragma unroll
            for (int dx = 0; dx < 3; dx++) {
                u64 wt = wv[dy * 3 + dx];
                acc0 = ffma2(ip[0 + dy][dx], wt, acc0);
                acc1 = ffma2(ip[1 + dy][dx], wt, acc1);
                acc2 = ffma2(ip[2 + dy][dx], wt, acc2);
                acc3 = ffma2(ip[3 + dy][dx], wt, acc3);
            }
        }
        st_cs64(outp,       acc0);
        st_cs64(outp + OUT, acc1);
        if (rv2) st_cs64(outp + 2 * OUT, acc2);
        if (rv3) st_cs64(outp + 3 * OUT, acc3);
        outp += PLANE_OUT;
    }
}

// ===================== launch =====================
extern "C" void kernel_launch(void* const* d_in, const int* in_sizes, int n_in,
                              void* d_out, int out_size) {
    const float* x = (const float*)d_in[0];
    const float* w = (const float*)d_in[1];
    float* out = (float*)d_out;

    rotw_kernel<<<8, 256>>>(w);    // 192*10 = 1920 slots

    dim3 grid(1,
              (OUT + TH - 1) / TH,   // 28 full-width row tiles
              32 * 3);               // 96 (n,m) planes
    conv_kernel<<<grid, 224>>>(x, out);
}

// round 11
// speedup vs baseline: 1.4341x; 1.0763x over previous
#include <cuda_runtime.h>

// ===================== Problem constants =====================
// M=3, N=8, G=8, K=3
// x: (32, 3, 224, 224) f32   w: (24, 1, 3, 3) f32
// out: (32, 192, 222, 222) f32, grouped conv: out channel o uses in channel o/64

#define IMG 224
#define OUT 222
#define NCH 192
#define PLANE_OUT (OUT*OUT)        // 49284

typedef unsigned long long u64;

// duplicated rotated weights (w,w) as u64, padded layout [192][10]:
// g_rotw2[o*10 + j], j<9 real (dy*3+dx), j==9 zero pad -> 80B stride, 16B aligned
__device__ u64 g_rotw2[192 * 10];

__device__ __forceinline__ u64 ffma2(u64 a, u64 b, u64 c) {
    u64 d;
    asm("fma.rn.f32x2 %0, %1, %2, %3;" : "=l"(d) : "l"(a), "l"(b), "l"(c));
    return d;
}
__device__ __forceinline__ u64 pack2(float lo, float hi) {
    u64 d;
    asm("mov.b64 %0, {%1, %2};" : "=l"(d) : "f"(lo), "f"(hi));
    return d;
}
__device__ __forceinline__ void unpack2(u64 v, float& lo, float& hi) {
    asm("mov.b64 {%0, %1}, %2;" : "=f"(lo), "=f"(hi) : "l"(v));
}
// streaming store: output is write-once, never re-read -> evict-first in L2
__device__ __forceinline__ void st_cs64(float* p, u64 v) {
    asm volatile("st.global.cs.b64 [%0], %1;" :: "l"(p), "l"(v) : "memory");
}

// ===================== Kernel 1: rotate weights =====================
__global__ void rotw_kernel(const float* __restrict__ w) {
    int t = blockIdx.x * blockDim.x + threadIdx.x;
    if (t >= 192 * 10) return;
    int o = t / 10, j = t % 10;
    if (j == 9) { g_rotw2[t] = 0ull; return; }   // pad slot
    int mn = o >> 3, g = o & 7;
    int hh = j / 3, ww = j % 3;

    // angle: linspace(-90, 90, 8)[g] degrees -> radians (double, like numpy)
    double ang = (-90.0 + (180.0 / 7.0) * (double)g) * 0.017453292519943295;
    float c = (float)cos(ang);
    float s = (float)sin(ang);

    float cx = (2.0f * ww + 1.0f) / 3.0f - 1.0f;
    float cy = (2.0f * hh + 1.0f) / 3.0f - 1.0f;
    float gx = c * cx - s * cy;
    float gy = s * cx + c * cy;

    float ix = ((gx + 1.0f) * 3.0f - 1.0f) * 0.5f;
    float iy = ((gy + 1.0f) * 3.0f - 1.0f) * 0.5f;
    float x0f = floorf(ix), y0f = floorf(iy);
    int   x0  = (int)x0f,   y0  = (int)y0f;
    float wx1 = ix - x0f, wy1 = iy - y0f;
    float wx0 = 1.0f - wx1, wy0 = 1.0f - wy1;

    const float* wp = w + mn * 9;
    float v00 = 0.f, v10 = 0.f, v01 = 0.f, v11 = 0.f;
    int x1 = x0 + 1, y1 = y0 + 1;
    bool bx0 = (x0 >= 0 && x0 < 3), bx1 = (x1 >= 0 && x1 < 3);
    bool by0 = (y0 >= 0 && y0 < 3), by1 = (y1 >= 0 && y1 < 3);
    if (bx0 && by0) v00 = wp[y0 * 3 + x0];
    if (bx1 && by0) v10 = wp[y0 * 3 + x1];
    if (bx0 && by1) v01 = wp[y1 * 3 + x0];
    if (bx1 && by1) v11 = wp[y1 * 3 + x1];

    float v = v00 * (wx0 * wy0) + v10 * (wx1 * wy0)
            + v01 * (wx0 * wy1) + v11 * (wx1 * wy1);

    g_rotw2[t] = pack2(v, v);
}

// ===================== Kernel 2: grouped conv, FULL-WIDTH 222x6 tiles =====================
// 222 = 37*6 exactly -> 37 y-tiles, zero row predicates, zero input clamping
// (max input row needed = 216+7 = 223 < 224).
// CTA: 224 threads = 112 x-threads x 2 y-threads; thread = 1 col-pair x 3 rows.
// Warp = 32 consecutive col-pairs -> contiguous 256B STG segments (.cs streaming).
// Weights: 4x LDS.128 + 1x LDS.64 per channel (80B padded stride).
// Grid 3552 CTAs / (148 SM x 5 CTA) = 4.80 waves -> 96% wave utilization.
#define TH 6
#define IN_H 8     // 6 + 2 halo rows

__global__ void __launch_bounds__(224)
conv_kernel(const float* __restrict__ x, float* __restrict__ out) {
    __shared__ __align__(16) float s_in[IN_H * IMG];   // 7168 B
    __shared__ __align__(16) u64   s_w[64 * 10];       // 5120 B

    int nm  = blockIdx.z;          // n*3 + m
    int m   = nm % 3;
    int ty0 = blockIdx.y * TH;     // first output row of tile (0..216)
    int tid = threadIdx.x;

    const float* xp = x + (size_t)nm * (IMG * IMG);

    // cooperative input load: 224 threads = exactly one full 896B row per pass.
    // Rows ty0..ty0+7 all exist (ty0 <= 216) -> no clamp.
    for (int i = tid; i < IN_H * IMG; i += 224) {
        int r  = i / IMG, cc = i % IMG;
        s_in[i] = xp[(ty0 + r) * IMG + cc];
    }
    // weights for this group (padded duplicated-pair layout, 80B/channel)
    {
        const u64* gw = g_rotw2 + (size_t)m * 64 * 10;
        for (int i = tid; i < 64 * 10; i += 224) s_w[i] = gw[i];
    }
    __syncthreads();

    int xi = tid % 112;            // col-pair index
    int yi = tid / 112;            // 0..1
    if (xi >= 111) return;         // pair 111 = cols 222-223 (invalid); no syncs follow
    int ox = 2 * xi;
    int ly = 3 * yi;               // 0 or 3
    int oy = ty0 + ly;             // rows oy..oy+2 always valid (oy <= 219)

    // register-resident input pairs: rows ly..ly+4, 3 overlapping pairs each
    u64 ip[5][3];
#pragma unroll
    for (int r = 0; r < 5; r++) {
        const u64* p = (const u64*)&s_in[(ly + r) * IMG + ox];   // 8B aligned
        u64 a = p[0], b = p[1];
        float a0, a1, a2, a3;
        unpack2(a, a0, a1);
        unpack2(b, a2, a3);
        ip[r][0] = a;
        ip[r][1] = pack2(a1, a2);
        ip[r][2] = b;
    }

    int n = nm / 3;
    float* outp = out + (size_t)(n * NCH + m * 64) * PLANE_OUT
                      + (size_t)oy * OUT + ox;

    for (int c = 0; c < 64; c++) {
        // 5 vector LDS: 80B stride keeps rows 16B aligned
        const u64* wc = &s_w[c * 10];
        ulonglong2 wA = *(const ulonglong2*)(wc + 0);   // w0 w1
        ulonglong2 wB = *(const ulonglong2*)(wc + 2);   // w2 w3
        ulonglong2 wC = *(const ulonglong2*)(wc + 4);   // w4 w5
        ulonglong2 wD = *(const ulonglong2*)(wc + 6);   // w6 w7
        u64 w8 = wc[8];
        u64 wv[9] = { wA.x, wA.y, wB.x, wB.y, wC.x, wC.y, wD.x, wD.y, w8 };

        u64 acc0 = 0, acc1 = 0, acc2 = 0;
#pragma unroll
        for (int dy = 0; dy < 3; dy++) {
#pragma unroll
            for (int dx = 0; dx < 3; dx++) {
                u64 wt = wv[dy * 3 + dx];
                acc0 = ffma2(ip[0 + dy][dx], wt, acc0);
                acc1 = ffma2(ip[1 + dy][dx], wt, acc1);
                acc2 = ffma2(ip[2 + dy][dx], wt, acc2);
            }
        }
        st_cs64(outp,           acc0);
        st_cs64(outp + OUT,     acc1);
        st_cs64(outp + 2 * OUT, acc2);
        outp += PLANE_OUT;
    }
}

// ===================== launch =====================
extern "C" void kernel_launch(void* const* d_in, const int* in_sizes, int n_in,
                              void* d_out, int out_size) {
    const float* x = (const float*)d_in[0];
    const float* w = (const float*)d_in[1];
    float* out = (float*)d_out;

    rotw_kernel<<<8, 256>>>(w);    // 192*10 = 1920 slots

    dim3 grid(1,
              37,                  // 222/6 exact full-width row tiles
              32 * 3);             // 96 (n,m) planes
    conv_kernel<<<grid, 224>>>(x, out);
}